// round 11
// baseline (speedup 1.0000x reference)
#include <cuda_runtime.h>
#include <cstdint>
#include <cstddef>

#define NPTS 4096
#define DIM  64
#define NBLK 128     // persistent blocks (<=148 SMs, 1 block/SM -> co-resident)
#define TPB  1024

// ---------------------------------------------------------------------------
// Scratch (allocation-free rule: __device__ globals)
// ---------------------------------------------------------------------------
__device__ float g_sq[NPTS];
__device__ unsigned short g_d2b[(size_t)NPTS * NPTS]; // 32 MB bf16-trunc d^2
__device__ unsigned g_eid[NPTS];                      // winning edge ids
__device__ unsigned g_bmin[NPTS * 32];                // per-(row,128col) mins
__device__ unsigned long long g_best[3][NPTS];        // triple-buffered keys
__device__ int          g_bar_cnt;
__device__ volatile int g_bar_gen;

static __device__ __forceinline__ float inf32() { return __int_as_float(0x7f800000); }
static __device__ __forceinline__ unsigned long long umin64(unsigned long long a,
                                                            unsigned long long b) {
    return a < b ? a : b;
}
// global key = (bf16 d2 bits << 24) | (min(u,v)<<12) | max(u,v)
// globally unique; identical from both endpoints => only mutual 2-cycles.
static __device__ __forceinline__ unsigned long long mkkey(unsigned wbits,
                                                           unsigned a, unsigned b) {
    unsigned lo = min(a, b), hi = max(a, b);
    return ((unsigned long long)wbits << 24) | (lo << 12) | hi;
}
// local row key (w16<<16|j) of row c -> global canonical key
static __device__ __forceinline__ unsigned long long loc2key(unsigned ck, unsigned c) {
    if (ck == 0xFFFFFFFFu) return ~0ull;
    return mkkey(ck >> 16, c, ck & 0xFFFFu);
}

static __device__ __forceinline__ void gridbar() {
    __syncthreads();
    if (threadIdx.x == 0) {
        __threadfence();
        int gen = g_bar_gen;
        if (atomicAdd(&g_bar_cnt, 1) == NBLK - 1) {
            g_bar_cnt = 0;
            __threadfence();
            g_bar_gen = gen + 1;
        } else {
            while (g_bar_gen == gen) { }
        }
        __threadfence();
    }
    __syncthreads();
}

// ---------------------------------------------------------------------------
// Kernel 1: warp-per-row squared norms + clear best buffers + barrier reset
// ---------------------------------------------------------------------------
__global__ void k_init(const float* __restrict__ p) {
    const int t   = threadIdx.x;
    const int gt  = blockIdx.x * TPB + t;
    const int row = gt >> 5;
    const int ln  = gt & 31;

    if (gt == 0) { g_bar_cnt = 0; g_bar_gen = 0; }
    if (gt < 3 * NPTS) ((unsigned long long*)g_best)[gt] = ~0ull;

    float2 v = *(const float2*)(p + (size_t)row * DIM + ln * 2);
    float acc = fmaf(v.x, v.x, v.y * v.y);
#pragma unroll
    for (int s = 16; s > 0; s >>= 1)
        acc += __shfl_down_sync(0xFFFFFFFFu, acc, s);
    if (ln == 0) g_sq[row] = acc;
}

// ---------------------------------------------------------------------------
// Kernel 2: d2 matrix (128x128 tile, 8x8/thread, packed f32x2 FMA), fp32
// compute, bf16-TRUNCATED u16 store (order-preserving for positive f32),
// fused per-(row, col-block) u32 min epilogue -> g_bmin (w16<<16|j).
// ---------------------------------------------------------------------------
__global__ void k_d2(const float* __restrict__ p) {
    __shared__ float As[32][128];
    __shared__ float Bs[32][128];

    const int t  = threadIdx.x;          // 0..255
    const int tx = t & 15;
    const int ty = t >> 4;
    const int i0 = blockIdx.y * 128;
    const int j0 = blockIdx.x * 128;

    const int lr = t >> 1;
    const int lc = (t & 1) * 16;

    unsigned long long acc2[8][4];
#pragma unroll
    for (int m = 0; m < 8; m++)
#pragma unroll
        for (int n = 0; n < 4; n++) acc2[m][n] = 0ull;

#pragma unroll
    for (int k0 = 0; k0 < DIM; k0 += 32) {
#pragma unroll
        for (int q = 0; q < 4; q++) {
            int c = lc + q * 4;
            float4 va = *(const float4*)(p + (size_t)(i0 + lr) * DIM + k0 + c);
            As[c + 0][lr] = va.x; As[c + 1][lr] = va.y;
            As[c + 2][lr] = va.z; As[c + 3][lr] = va.w;
            float4 vb = *(const float4*)(p + (size_t)(j0 + lr) * DIM + k0 + c);
            Bs[c + 0][lr] = vb.x; Bs[c + 1][lr] = vb.y;
            Bs[c + 2][lr] = vb.z; Bs[c + 3][lr] = vb.w;
        }
        __syncthreads();

#pragma unroll
        for (int k = 0; k < 32; k++) {
            uint4 a0 = *(const uint4*)&As[k][ty * 8];
            uint4 a1 = *(const uint4*)&As[k][ty * 8 + 4];
            unsigned au[8] = {a0.x, a0.y, a0.z, a0.w, a1.x, a1.y, a1.z, a1.w};
            ulonglong2 b0 = *(const ulonglong2*)&Bs[k][tx * 8];
            ulonglong2 b1 = *(const ulonglong2*)&Bs[k][tx * 8 + 4];
            unsigned long long bp[4] = {b0.x, b0.y, b1.x, b1.y};
#pragma unroll
            for (int m = 0; m < 8; m++) {
                unsigned long long ap;
                asm("mov.b64 %0, {%1, %1};" : "=l"(ap) : "r"(au[m]));
#pragma unroll
                for (int n = 0; n < 4; n++)
                    asm("fma.rn.f32x2 %0, %1, %2, %0;"
                        : "+l"(acc2[m][n]) : "l"(ap), "l"(bp[n]));
            }
        }
        __syncthreads();
    }

    float sqi[8], sqj[8];
#pragma unroll
    for (int m = 0; m < 8; m++) sqi[m] = g_sq[i0 + ty * 8 + m];
#pragma unroll
    for (int n = 0; n < 8; n++) sqj[n] = g_sq[j0 + tx * 8 + n];

#pragma unroll
    for (int m = 0; m < 8; m++) {
        const int row = i0 + ty * 8 + m;
        unsigned hw[8];
#pragma unroll
        for (int n = 0; n < 4; n++) {
            unsigned lo, hi;
            asm("mov.b64 {%0, %1}, %2;" : "=r"(lo), "=r"(hi) : "l"(acc2[m][n]));
            float d0 = __uint_as_float(lo), d1 = __uint_as_float(hi);
            float o0 = fmaxf(sqi[m] + sqj[2 * n + 0] - 2.f * d0, 0.f);
            float o1 = fmaxf(sqi[m] + sqj[2 * n + 1] - 2.f * d1, 0.f);
            hw[2 * n + 0] = __float_as_uint(o0) >> 16;   // bf16 truncation
            hw[2 * n + 1] = __float_as_uint(o1) >> 16;
        }
        uint4 pack;
        pack.x = hw[0] | (hw[1] << 16);
        pack.y = hw[2] | (hw[3] << 16);
        pack.z = hw[4] | (hw[5] << 16);
        pack.w = hw[6] | (hw[7] << 16);
        *(uint4*)(g_d2b + (size_t)row * NPTS + j0 + tx * 8) = pack;

        // fused per-(row, 128-col block) u32 min (w16<<16|j), diag excluded
        unsigned cand = 0xFFFFFFFFu;
#pragma unroll
        for (int n = 0; n < 8; n++) {
            unsigned jj = (unsigned)(j0 + tx * 8 + n);
            if (jj != (unsigned)row)
                cand = min(cand, (hw[n] << 16) | jj);
        }
#pragma unroll
        for (int s = 8; s > 0; s >>= 1)
            cand = min(cand, __shfl_down_sync(0xFFFFFFFFu, cand, s, 16));
        if (tx == 0) g_bmin[row * 32 + blockIdx.x] = cand;
    }
}

// ---------------------------------------------------------------------------
// Kernel 3: persistent Boruvka + exact-length recompute + sort.
// Selection per warp/row via u32 block-min bounds; only blocks that can hide
// a better out-of-comp edge get a 128-entry u16 scan. Exact selection under
// the (bf16, canonical-id) total order. One grid barrier per round; hook over
// active components, all blocks redundantly in their own shared memory.
// ---------------------------------------------------------------------------
__global__ void __launch_bounds__(TPB, 1) k_mst(const float* __restrict__ p,
                                                float* __restrict__ out) {
    __shared__ unsigned short comp[NPTS];     // 8 KB persistent labels
    __shared__ int par[NPTS];                 // 16 KB; reused as float sort buf
    __shared__ unsigned short act[2][NPTS];   // 16 KB ping-pong active comps
    __shared__ int s_na2;                     // next active count
    __shared__ int s_cnt;                     // block0 edge counter

    const int t    = threadIdx.x;
    const int wid  = t >> 5;
    const int lane = t & 31;
    const int row  = blockIdx.x * 32 + wid;

    for (int i = t; i < NPTS; i += TPB) {
        comp[i] = (unsigned short)i;
        act[0][i] = (unsigned short)i;
    }
    if (t == 0) s_cnt = 0;
    __syncthreads();

    int na = NPTS;

    for (int k = 0; k < 12; k++) {
        const int pp = k & 1;

        // ---- selection via u32 block-min bounds ----
        {
            const unsigned myc = comp[row];
            unsigned e = g_bmin[row * 32 + lane];
            unsigned ej = e & 0xFFFFu;
            bool oc = comp[ej] != myc;                 // partner out-of-comp?
            unsigned cand = oc ? e : 0xFFFFFFFFu;
#pragma unroll
            for (int s = 16; s > 0; s >>= 1)
                cand = min(cand, __shfl_xor_sync(0xFFFFFFFFu, cand, s));

            unsigned scanmask = __ballot_sync(0xFFFFFFFFu, !oc && e < cand);
            unsigned best = cand;
            while (scanmask) {
                int b = __ffs(scanmask) - 1;
                scanmask &= scanmask - 1;
                const unsigned long long* r8 = (const unsigned long long*)
                    (g_d2b + (size_t)row * NPTS + b * 128);
                unsigned long long w4 = r8[lane];      // 4 cols per lane
                const unsigned cb = (unsigned)(b * 128 + lane * 4);
#pragma unroll
                for (int q = 0; q < 4; q++) {
                    unsigned w = (unsigned)((w4 >> (16 * q)) & 0xFFFFu);
                    unsigned jj = cb + q;
                    if (comp[jj] != myc)
                        best = min(best, (w << 16) | jj);
                }
            }
#pragma unroll
            for (int s = 16; s > 0; s >>= 1)
                best = min(best, __shfl_down_sync(0xFFFFFFFFu, best, s));
            if (lane == 0 && best != 0xFFFFFFFFu)
                atomicMin(&g_best[k % 3][myc], loc2key(best, (unsigned)row));
        }
        gridbar();

        // ---- hook over ACTIVE components (all blocks, redundant) ----
        const unsigned long long* B = g_best[k % 3];
        for (int idx = t; idx < na; idx += TPB) { int c = act[pp][idx]; par[c] = c; }
        if (t == 0) s_na2 = 0;
        __syncthreads();

        for (int idx = t; idx < na; idx += TPB) {
            int c = act[pp][idx];
            unsigned long long key = B[c];
            bool isroot = false;
            if (key != ~0ull) {
                unsigned id = (unsigned)(key & 0xFFFFFFu);
                int u = (int)(id >> 12), v = (int)(id & 0xFFFu);
                int cu = comp[u], cv = comp[v];
                int other = (cu == c) ? cv : cu;
                bool mutual = (B[other] == key);
                if (!mutual)        par[c] = other;
                else if (c > other) par[c] = other;
                else                isroot = true;
                if (blockIdx.x == 0 && (!mutual || c < other)) {
                    int e = atomicAdd(&s_cnt, 1);
                    g_eid[e] = id;
                }
            } else {
                isroot = true;
            }
            if (isroot) {
                int pos = atomicAdd(&s_na2, 1);
                act[pp ^ 1][pos] = (unsigned short)c;
            }
        }
        __syncthreads();

        // pointer jumping over active list, early exit on convergence
        for (int it = 0; it < 12; it++) {
            int chg = 0;
            for (int idx = t; idx < na; idx += TPB) {
                int c = act[pp][idx];
                int p1 = par[c];
                int p2 = par[p1];
                if (p2 != p1) { par[c] = p2; chg = 1; }
            }
            if (!__syncthreads_or(chg)) break;
        }

        // relabel all vertices + clear this block's slice of buffer (k+2)%3
        for (int i = t; i < NPTS; i += TPB)
            comp[i] = (unsigned short)par[comp[i]];
        if (t < 32) g_best[(k + 2) % 3][blockIdx.x * 32 + t] = ~0ull;
        __syncthreads();

        na = s_na2;
        if (na <= 1) break;
    }

    if (blockIdx.x != 0) return;

    // ---- exact fp32 lengths for the 4095 winning edges, then bitonic sort --
    __syncthreads();
    float* sh = (float*)par;
    for (int e = t; e < NPTS; e += TPB) {
        if (e < NPTS - 1) {
            unsigned id = g_eid[e];
            int u = (int)(id >> 12), v = (int)(id & 0xFFFu);
            const float4* pu = (const float4*)(p + (size_t)u * DIM);
            const float4* pv = (const float4*)(p + (size_t)v * DIM);
            float dot = 0.f;
#pragma unroll
            for (int q = 0; q < DIM / 4; q++) {
                float4 a = pu[q], b = pv[q];
                dot = fmaf(a.x, b.x, dot);
                dot = fmaf(a.y, b.y, dot);
                dot = fmaf(a.z, b.z, dot);
                dot = fmaf(a.w, b.w, dot);
            }
            sh[e] = sqrtf(fmaxf(g_sq[u] + g_sq[v] - 2.f * dot, 0.f));
        } else {
            sh[e] = inf32();
        }
    }
    __syncthreads();

    for (int kk = 2; kk <= NPTS; kk <<= 1) {
        for (int j = kk >> 1; j > 0; j >>= 1) {
#pragma unroll
            for (int tt = 0; tt < 2; tt++) {
                int u = t + tt * TPB;
                int i = ((u & ~(j - 1)) << 1) | (u & (j - 1));
                int l = i | j;
                float a = sh[i], c = sh[l];
                bool up = (i & kk) == 0;
                if ((a > c) == up) { sh[i] = c; sh[l] = a; }
            }
            __syncthreads();
        }
    }
    for (int m = t; m < NPTS - 1; m += TPB) out[m] = sh[m];
}

// ---------------------------------------------------------------------------
extern "C" void kernel_launch(void* const* d_in, const int* in_sizes, int n_in,
                              void* d_out, int out_size) {
    (void)in_sizes; (void)n_in; (void)out_size;
    const float* points = (const float*)d_in[0];
    float* out = (float*)d_out;

    k_init<<<NPTS * 32 / TPB, TPB>>>(points);            // 128 x 1024
    k_d2<<<dim3(NPTS / 128, NPTS / 128), 256>>>(points); // 32x32 x 256
    k_mst<<<NBLK, TPB>>>(points, out);
}